// round 5
// baseline (speedup 1.0000x reference)
#include <cuda_runtime.h>

#define NB 16384
#define NT 1024
#define HH 64
#define TPB 128
#define WPB 4                 // warps/block
#define EPW 8                 // elements/warp (4 g-groups x 2 elements)
#define EPB (WPB * EPW)       // 32 elements/block
#define GRID (NB / EPB)       // 512 blocks
#define HSTR 10               // hT row stride (words): 8B-aligned, bank-spread

typedef unsigned long long u64;

// ---- packed f32x2 (Blackwell FFMA2 path, PTX-only) ----
static __device__ __forceinline__ u64 fma2(u64 a, u64 b, u64 c) {
    u64 d;
    asm("fma.rn.f32x2 %0, %1, %2, %3;" : "=l"(d) : "l"(a), "l"(b), "l"(c));
    return d;
}
static __device__ __forceinline__ u64 dup2(float a) {
    u64 d;
    asm("mov.b64 %0, {%1, %1};" : "=l"(d) : "f"(a));
    return d;
}
static __device__ __forceinline__ void upk(u64 v, float& a, float& b) {
    asm("mov.b64 {%0, %1}, %2;" : "=f"(a), "=f"(b) : "l"(v));
}

#define LOG2E2 2.8853900817779268f  // 2*log2(e), folded into W1/b1/W2/b2

// tanh with PRE-SCALED argument: expects a = 2*log2(e)*x.
// tanh(x) = 1 - 2/(exp(2x)+1) = 1 - 2/(2^a + 1). Validated rel_err ~3.6e-7.
static __device__ __forceinline__ float tanh_pre(float a) {
    float e, r;
    asm("ex2.approx.f32 %0, %1;" : "=f"(e) : "f"(a));
    asm("rcp.approx.f32 %0, %1;" : "=f"(r) : "f"(e + 1.0f));
    return fmaf(-2.0f, r, 1.0f);
}

struct __align__(16) SW {
    // W2 (x LOG2E2) transposed, 16B-block permutation p(b) = (b&1)*8 + (b>>1):
    // lane o's two LDS.128 at [k][4o] and [k][32+4o] give j = 8o..8o+7, and
    // each instruction's 8 distinct 16B chunks span all 32 banks.
    float W2s[HH][HH];
    float W1xs[HH], W1ys[HH], b1s[HH];  // x LOG2E2
    float b2s[HH];                       // x LOG2E2
    float W3P[HH * 2];                   // W3P[2u+d] = W3[d][u] (unscaled)
    float b3[2];
    float dt[NT];
};

__device__ __constant__ float cA[5][5] = {
    {(float)(1.0 / 5.0), 0.f, 0.f, 0.f, 0.f},
    {(float)(3.0 / 40.0), (float)(9.0 / 40.0), 0.f, 0.f, 0.f},
    {(float)(44.0 / 45.0), (float)(-56.0 / 15.0), (float)(32.0 / 9.0), 0.f, 0.f},
    {(float)(19372.0 / 6561.0), (float)(-25360.0 / 2187.0),
     (float)(64448.0 / 6561.0), (float)(-212.0 / 729.0), 0.f},
    {(float)(9017.0 / 3168.0), (float)(-355.0 / 33.0),
     (float)(46732.0 / 5247.0), (float)(49.0 / 176.0),
     (float)(-5103.0 / 18656.0)},
};

__global__ void __launch_bounds__(TPB)
ode_kernel(const float* __restrict__ y0, const float* __restrict__ ts,
           const float* __restrict__ W1, const float* __restrict__ b1,
           const float* __restrict__ W2, const float* __restrict__ b2,
           const float* __restrict__ W3, const float* __restrict__ b3,
           float* __restrict__ out) {
    __shared__ SW s;
    __shared__ __align__(16) float hT[WPB][HH][HSTR];  // [unit][elem], padded

    const int tid = threadIdx.x;
    for (int i = tid; i < HH * HH; i += TPB) {
        const int j = i >> 6, k = i & 63;        // W2[j][k] -> transposed
        const int b = j >> 2, w = j & 3;
        const int p = ((b & 1) << 3) + (b >> 1); // block permutation
        s.W2s[k][p * 4 + w] = W2[i] * LOG2E2;
    }
    for (int i = tid; i < HH; i += TPB) {
        s.W1xs[i] = W1[2 * i] * LOG2E2;
        s.W1ys[i] = W1[2 * i + 1] * LOG2E2;
        s.b1s[i] = b1[i] * LOG2E2;
        s.b2s[i] = b2[i] * LOG2E2;
    }
    for (int i = tid; i < HH * 2; i += TPB) {
        const int d = i >> 6, u = i & 63;
        s.W3P[2 * u + d] = W3[i];
    }
    if (tid < 2) s.b3[tid] = b3[tid];
    for (int i = tid; i < NT - 1; i += TPB) s.dt[i] = ts[i + 1] - ts[i];
    __syncthreads();

    const int wid = tid >> 5, lane = tid & 31;
    const int o = lane & 7;        // hidden slice: units/j 8o..8o+7
    const int g = lane >> 3;       // element pair-group
    float* hw = &hT[wid][0][0];
    const int eloc = 2 * g;                          // warp-local element base
    const int e0 = blockIdx.x * EPB + wid * EPW + eloc;

    float yx[2], yy[2];
    {
        const float4 v = *reinterpret_cast<const float4*>(
            &reinterpret_cast<const float2*>(y0)[e0]);
        yx[0] = v.x; yy[0] = v.y;
        yx[1] = v.z; yy[1] = v.w;
    }

    float2* o2 = reinterpret_cast<float2*>(out);
    if (o == 0)  // SaveAt includes the initial state
        *(float4*)&o2[e0] = make_float4(yx[0], yy[0], yx[1], yy[1]);

    const float B1 = (float)(35.0 / 384.0);
    const float B3 = (float)(500.0 / 1113.0);
    const float B4 = (float)(125.0 / 192.0);
    const float B5 = (float)(-2187.0 / 6784.0);
    const float B6 = (float)(11.0 / 84.0);

    for (int t = 0; t < NT - 1; t++) {
        const float dt = s.dt[t];
        float sx[2], sy[2];
        float kxr[6][2], kyr[6][2];   // RK stage values, register-resident
        sx[0] = yx[0]; sy[0] = yy[0];
        sx[1] = yx[1]; sy[1] = yy[1];

#pragma unroll 1  // single inlined f-eval body (I$-friendly)
        for (int st = 0; st < 6; st++) {
            __syncwarp();  // prior stage's hT readers are done (WAR)

            // ---- layer 1: units 8o+i, elements eloc..eloc+1 -> hT ----
#pragma unroll
            for (int i = 0; i < 8; i++) {
                const int u = 8 * o + i;
                const float wx = s.W1xs[u], wy = s.W1ys[u], bb = s.b1s[u];
                const float a0 = fmaf(sx[0], wx, fmaf(sy[0], wy, bb));
                const float a1 = fmaf(sx[1], wx, fmaf(sy[1], wy, bb));
                *(float2*)&hw[u * HSTR + eloc] =
                    make_float2(tanh_pre(a0), tanh_pre(a1));
            }
            __syncwarp();  // hT complete (RAW)

            // ---- layer 2: acc[m][p], unit-pairs (8o+2p, 8o+2p+1) ----
            u64 acc[2][4];
#pragma unroll
            for (int p = 0; p < 4; p++) {
                const u64 bp = *(const u64*)&s.b2s[8 * o + 2 * p];
                acc[0][p] = bp;
                acc[1][p] = bp;
            }
#pragma unroll 8
            for (int k = 0; k < HH; k++) {
                const float2 hv = *(const float2*)&hw[k * HSTR + eloc];
                const u64 h0 = dup2(hv.x), h1 = dup2(hv.y);
                const float4 wA = *(const float4*)&s.W2s[k][4 * o];
                const float4 wB = *(const float4*)&s.W2s[k][32 + 4 * o];
                const u64 w0 = ((const u64*)&wA)[0], w1 = ((const u64*)&wA)[1];
                const u64 w2v = ((const u64*)&wB)[0], w3v = ((const u64*)&wB)[1];
                acc[0][0] = fma2(h0, w0, acc[0][0]);
                acc[0][1] = fma2(h0, w1, acc[0][1]);
                acc[0][2] = fma2(h0, w2v, acc[0][2]);
                acc[0][3] = fma2(h0, w3v, acc[0][3]);
                acc[1][0] = fma2(h1, w0, acc[1][0]);
                acc[1][1] = fma2(h1, w1, acc[1][1]);
                acc[1][2] = fma2(h1, w2v, acc[1][2]);
                acc[1][3] = fma2(h1, w3v, acc[1][3]);
            }

            // ---- layer-2 tanh + layer 3 (partial over this lane's j's) ----
            u64 accP[2] = {0ull, 0ull};
#pragma unroll
            for (int p = 0; p < 4; p++) {
                const u64 wp0 = *(const u64*)&s.W3P[16 * o + 4 * p];
                const u64 wp1 = *(const u64*)&s.W3P[16 * o + 4 * p + 2];
#pragma unroll
                for (int m = 0; m < 2; m++) {
                    float a0, a1;
                    upk(acc[m][p], a0, a1);
                    accP[m] = fma2(dup2(tanh_pre(a0)), wp0, accP[m]);
                    accP[m] = fma2(dup2(tanh_pre(a1)), wp1, accP[m]);
                }
            }

            // xor-butterfly over the 8 o-lanes: every lane gets full (fx, fy)
#pragma unroll
            for (int m = 0; m < 2; m++) {
                float px, py;
                upk(accP[m], px, py);
                px += __shfl_xor_sync(0xffffffffu, px, 1);
                py += __shfl_xor_sync(0xffffffffu, py, 1);
                px += __shfl_xor_sync(0xffffffffu, px, 2);
                py += __shfl_xor_sync(0xffffffffu, py, 2);
                px += __shfl_xor_sync(0xffffffffu, px, 4);
                py += __shfl_xor_sync(0xffffffffu, py, 4);
                kxr[st][m] = px + s.b3[0];
                kyr[st][m] = py + s.b3[1];
            }

            if (st < 5) {  // next stage input (identical on all lanes)
#pragma unroll
                for (int m = 0; m < 2; m++) {
                    float ax = 0.f, ay = 0.f;
                    for (int i = 0; i <= st; i++) {
                        const float a = cA[st][i];
                        ax = fmaf(a, kxr[i][m], ax);
                        ay = fmaf(a, kyr[i][m], ay);
                    }
                    sx[m] = fmaf(dt, ax, yx[m]);
                    sy[m] = fmaf(dt, ay, yy[m]);
                }
            }
        }

        // ---- combine and advance ----
#pragma unroll
        for (int m = 0; m < 2; m++) {
            float ax = B1 * kxr[0][m], ay = B1 * kyr[0][m];
            ax = fmaf(B3, kxr[2][m], ax); ay = fmaf(B3, kyr[2][m], ay);
            ax = fmaf(B4, kxr[3][m], ax); ay = fmaf(B4, kyr[3][m], ay);
            ax = fmaf(B5, kxr[4][m], ax); ay = fmaf(B5, kyr[4][m], ay);
            ax = fmaf(B6, kxr[5][m], ax); ay = fmaf(B6, kyr[5][m], ay);
            yx[m] = fmaf(dt, ax, yx[m]);
            yy[m] = fmaf(dt, ay, yy[m]);
        }
        if (o == 0) {
            float2* orow = o2 + (size_t)(t + 1) * NB;
            *(float4*)&orow[e0] = make_float4(yx[0], yy[0], yx[1], yy[1]);
        }
    }
}

extern "C" void kernel_launch(void* const* d_in, const int* in_sizes, int n_in,
                              void* d_out, int out_size) {
    const float* y0 = (const float*)d_in[0];
    const float* ts = (const float*)d_in[1];
    const float* W1 = (const float*)d_in[2];
    const float* b1 = (const float*)d_in[3];
    const float* W2 = (const float*)d_in[4];
    const float* b2 = (const float*)d_in[5];
    const float* W3 = (const float*)d_in[6];
    const float* b3 = (const float*)d_in[7];
    ode_kernel<<<GRID, TPB>>>(y0, ts, W1, b1, W2, b2, W3, b3, (float*)d_out);
}